// round 1
// baseline (speedup 1.0000x reference)
#include <cuda_runtime.h>
#include <math.h>
#include <stdint.h>

// ---------------------------------------------------------------------------
// SpatioTemporalPerformerEncoder — fp32 baseline
// B=2, T=8, L=512 -> 8192 rows, D=512, H=8, dh=64, m=256, FF=2048, depth=4
// ---------------------------------------------------------------------------

#define Bc     2
#define Hc     8
#define Nc     4096           // tokens per batch (T*L)
#define Dc     512
#define DHc    64
#define Mc     256            // FAVOR+ features
#define FFc    2048
#define DEPTHc 4
#define ROWSc  8192           // B*Nc
#define BHc    16             // B*H
#define QKVW   1536

#define DN_CONST    0.35355339059327373f   // 64^-0.25
#define DIAG_SCALE  0.0625f                // 0.5*dn*dn
#define RATIO_CONST 0.0625f                // 256^-0.5
#define EPSK        1e-4f
#define LNEPS       1e-5f

// ------------------------- scratch (device globals) ------------------------
__device__ float g_ln  [(size_t)ROWSc * Dc];
__device__ float g_qkv [(size_t)ROWSc * QKVW];
__device__ float g_qp  [(size_t)BHc * Nc * Mc];
__device__ float g_kp  [(size_t)BHc * Nc * Mc];
__device__ float g_ff  [(size_t)ROWSc * FFc];
__device__ float g_ctx [BHc * Mc * DHc];
__device__ float g_ksum[BHc * Mc];
__device__ float g_kdiag[BHc * Nc];
__device__ float g_bmax[BHc * Nc];
__device__ float g_hmax[BHc];
__device__ float g_dinv[BHc * Nc];

// ------------------------------ copy x -> h --------------------------------
__global__ void copy_kernel(const float* __restrict__ x, float* __restrict__ h) {
    size_t i = (size_t)blockIdx.x * 256 + threadIdx.x;
    h[i] = x[i];
}

// ------------------------------- layernorm ---------------------------------
// one block (256 threads) per row of 512
__global__ __launch_bounds__(256)
void ln_kernel(const float* __restrict__ x, const float* __restrict__ g,
               const float* __restrict__ b, float* __restrict__ out) {
    int row = blockIdx.x;
    int t = threadIdx.x;
    const float* xr = x + (size_t)row * Dc;
    float v0 = xr[t], v1 = xr[t + 256];

    __shared__ float red[256];
    red[t] = v0 + v1;
    __syncthreads();
#pragma unroll
    for (int o = 128; o > 0; o >>= 1) {
        if (t < o) red[t] += red[t + o];
        __syncthreads();
    }
    float mu = red[0] * (1.0f / Dc);
    __syncthreads();

    float d0 = v0 - mu, d1 = v1 - mu;
    red[t] = d0 * d0 + d1 * d1;
    __syncthreads();
#pragma unroll
    for (int o = 128; o > 0; o >>= 1) {
        if (t < o) red[t] += red[t + o];
        __syncthreads();
    }
    float rs = rsqrtf(red[0] * (1.0f / Dc) + LNEPS);

    float* orow = out + (size_t)row * Dc;
    orow[t]       = d0 * rs * g[t]       + b[t];
    orow[t + 256] = d1 * rs * g[t + 256] + b[t + 256];
}

// --------------------------------- SGEMM -----------------------------------
// C[M,N] = A[M,K] * B[K,N] + bias[N]  (+ gelu / + residual)
// BM=BN=128, BK=16, 256 threads, 8x8 per thread.
// M%128==0, N%128==0, K%16==0 for all call sites.
#define EPI_NONE 0
#define EPI_GELU 1
#define EPI_ADD  2

template <int EPI>
__global__ __launch_bounds__(256)
void sgemm(const float* __restrict__ A, const float* __restrict__ B,
           const float* __restrict__ bias, const float* __restrict__ R,
           float* __restrict__ C, int M, int N, int K) {
    __shared__ float As[16][132];
    __shared__ float Bs[16][128];

    int tid = threadIdx.x;
    int m0 = blockIdx.y * 128, n0 = blockIdx.x * 128;

    int ar = tid >> 2;          // 0..63
    int ac = (tid & 3) * 4;     // 0,4,8,12
    int br = tid >> 5;          // 0..7
    int bc = (tid & 31) * 4;    // 0..124

    const float* Aptr = A + (size_t)(m0 + ar) * K + ac;
    const float* Bptr = B + (size_t)br * N + n0 + bc;

    float acc[8][8];
#pragma unroll
    for (int i = 0; i < 8; i++)
#pragma unroll
        for (int j = 0; j < 8; j++) acc[i][j] = 0.0f;

    int tx = tid & 15, ty = tid >> 4;

    for (int k0 = 0; k0 < K; k0 += 16) {
        float4 a0 = *(const float4*)(Aptr);
        float4 a1 = *(const float4*)(Aptr + (size_t)64 * K);
        float4 b0 = *(const float4*)(Bptr);
        float4 b1 = *(const float4*)(Bptr + (size_t)8 * N);

        As[ac + 0][ar] = a0.x; As[ac + 1][ar] = a0.y;
        As[ac + 2][ar] = a0.z; As[ac + 3][ar] = a0.w;
        As[ac + 0][ar + 64] = a1.x; As[ac + 1][ar + 64] = a1.y;
        As[ac + 2][ar + 64] = a1.z; As[ac + 3][ar + 64] = a1.w;
        *(float4*)&Bs[br][bc]     = b0;
        *(float4*)&Bs[br + 8][bc] = b1;
        __syncthreads();

#pragma unroll
        for (int k = 0; k < 16; k++) {
            float a[8], bb[8];
            *(float4*)&a[0]  = *(float4*)&As[k][ty * 8];
            *(float4*)&a[4]  = *(float4*)&As[k][ty * 8 + 4];
            *(float4*)&bb[0] = *(float4*)&Bs[k][tx * 8];
            *(float4*)&bb[4] = *(float4*)&Bs[k][tx * 8 + 4];
#pragma unroll
            for (int i = 0; i < 8; i++)
#pragma unroll
                for (int j = 0; j < 8; j++)
                    acc[i][j] = fmaf(a[i], bb[j], acc[i][j]);
        }
        __syncthreads();
        Aptr += 16;
        Bptr += (size_t)16 * N;
    }

#pragma unroll
    for (int i = 0; i < 8; i++) {
        int row = m0 + ty * 8 + i;
#pragma unroll
        for (int j = 0; j < 8; j++) {
            int col = n0 + tx * 8 + j;
            float v = acc[i][j] + bias[col];
            if (EPI == EPI_GELU)
                v = 0.5f * v * (1.0f + erff(v * 0.70710678118654752f));
            if (EPI == EPI_ADD)
                v += R[(size_t)row * N + col];
            C[(size_t)row * N + col] = v;
        }
    }
}

// --------------------------- FAVOR+ query features -------------------------
// grid (8192 rows, 8 heads), 256 threads (one per feature m)
__global__ __launch_bounds__(256)
void featq_kernel(const float* __restrict__ qkv, const float* __restrict__ proj,
                  float* __restrict__ qp) {
    int row = blockIdx.x;          // b*Nc + n
    int h   = blockIdx.y;
    int t   = threadIdx.x;

    __shared__ float qs[64];
    __shared__ float red[64];
    __shared__ float wmax[8];
    __shared__ float s_diag, s_mx;

    const float* qr = qkv + (size_t)row * QKVW + h * DHc;
    if (t < 64) qs[t] = qr[t];
    __syncthreads();

    if (t < 64) red[t] = qs[t] * qs[t];
    __syncthreads();
    if (t < 32) {
        float v = red[t] + red[t + 32];
#pragma unroll
        for (int o = 16; o > 0; o >>= 1) v += __shfl_down_sync(0xffffffffu, v, o);
        if (t == 0) s_diag = v * DIAG_SCALE;
    }
    __syncthreads();

    const float4* p4 = (const float4*)(proj + (size_t)t * DHc);
    const float4* q4 = (const float4*)qs;
    float dot = 0.0f;
#pragma unroll
    for (int i = 0; i < 16; i++) {
        float4 pv = p4[i], qv = q4[i];
        dot = fmaf(pv.x, qv.x, dot);
        dot = fmaf(pv.y, qv.y, dot);
        dot = fmaf(pv.z, qv.z, dot);
        dot = fmaf(pv.w, qv.w, dot);
    }
    float dd = dot * DN_CONST;

    float mx = dd;
#pragma unroll
    for (int o = 16; o > 0; o >>= 1) mx = fmaxf(mx, __shfl_xor_sync(0xffffffffu, mx, o));
    if ((t & 31) == 0) wmax[t >> 5] = mx;
    __syncthreads();
    if (t == 0) {
        float mm = wmax[0];
#pragma unroll
        for (int i = 1; i < 8; i++) mm = fmaxf(mm, wmax[i]);
        s_mx = mm;
    }
    __syncthreads();

    float val = RATIO_CONST * (expf(dd - s_diag - s_mx) + EPSK);
    int b = row >> 12, n = row & (Nc - 1);
    int bh = b * Hc + h;
    qp[((size_t)bh * Nc + n) * Mc + t] = val;
}

// ------------------------- key features pass 1 (dd, max, diag) -------------
__global__ __launch_bounds__(256)
void featk1_kernel(const float* __restrict__ qkv, const float* __restrict__ proj,
                   float* __restrict__ kp, float* __restrict__ kdiag,
                   float* __restrict__ bmax) {
    int row = blockIdx.x;
    int h   = blockIdx.y;
    int t   = threadIdx.x;

    __shared__ float ks[64];
    __shared__ float red[64];
    __shared__ float wmax[8];

    const float* kr = qkv + (size_t)row * QKVW + Dc + h * DHc;
    if (t < 64) ks[t] = kr[t];
    __syncthreads();

    int b = row >> 12, n = row & (Nc - 1);
    int bh = b * Hc + h;

    if (t < 64) red[t] = ks[t] * ks[t];
    __syncthreads();
    if (t < 32) {
        float v = red[t] + red[t + 32];
#pragma unroll
        for (int o = 16; o > 0; o >>= 1) v += __shfl_down_sync(0xffffffffu, v, o);
        if (t == 0) kdiag[(size_t)bh * Nc + n] = v * DIAG_SCALE;
    }

    const float4* p4 = (const float4*)(proj + (size_t)t * DHc);
    const float4* q4 = (const float4*)ks;
    float dot = 0.0f;
#pragma unroll
    for (int i = 0; i < 16; i++) {
        float4 pv = p4[i], qv = q4[i];
        dot = fmaf(pv.x, qv.x, dot);
        dot = fmaf(pv.y, qv.y, dot);
        dot = fmaf(pv.z, qv.z, dot);
        dot = fmaf(pv.w, qv.w, dot);
    }
    float dd = dot * DN_CONST;
    kp[((size_t)bh * Nc + n) * Mc + t] = dd;

    float mx = dd;
#pragma unroll
    for (int o = 16; o > 0; o >>= 1) mx = fmaxf(mx, __shfl_xor_sync(0xffffffffu, mx, o));
    if ((t & 31) == 0) wmax[t >> 5] = mx;
    __syncthreads();
    if (t == 0) {
        float mm = wmax[0];
#pragma unroll
        for (int i = 1; i < 8; i++) mm = fmaxf(mm, wmax[i]);
        bmax[(size_t)bh * Nc + n] = mm;
    }
}

// ------------------------- per-head global max reduce -----------------------
__global__ __launch_bounds__(256)
void hmax_kernel(const float* __restrict__ bmax, float* __restrict__ hmax) {
    int bh = blockIdx.x;
    int t = threadIdx.x;
    float m = -1e30f;
    for (int i = t; i < Nc; i += 256) m = fmaxf(m, bmax[(size_t)bh * Nc + i]);
#pragma unroll
    for (int o = 16; o > 0; o >>= 1) m = fmaxf(m, __shfl_xor_sync(0xffffffffu, m, o));
    __shared__ float w[8];
    if ((t & 31) == 0) w[t >> 5] = m;
    __syncthreads();
    if (t == 0) {
        float mm = w[0];
#pragma unroll
        for (int i = 1; i < 8; i++) mm = fmaxf(mm, w[i]);
        hmax[bh] = mm;
    }
}

// ------------------------- key features pass 2 (exp) -----------------------
__global__ __launch_bounds__(256)
void featk2_kernel(float* __restrict__ kp, const float* __restrict__ kdiag,
                   const float* __restrict__ hmax) {
    size_t i4 = (size_t)blockIdx.x * 256 + threadIdx.x;   // float4 index
    size_t idx = i4 * 4;
    int bh = (int)(idx >> 20);
    int n  = (int)((idx >> 8) & (Nc - 1));
    float sub = kdiag[(size_t)bh * Nc + n] + hmax[bh];
    float4 v = *(float4*)&kp[idx];
    v.x = RATIO_CONST * (expf(v.x - sub) + EPSK);
    v.y = RATIO_CONST * (expf(v.y - sub) + EPSK);
    v.z = RATIO_CONST * (expf(v.z - sub) + EPSK);
    v.w = RATIO_CONST * (expf(v.w - sub) + EPSK);
    *(float4*)&kp[idx] = v;
}

// ---------------------------- zero ctx / ksum ------------------------------
__global__ void zero_kernel(float* __restrict__ ctx, float* __restrict__ ksum) {
    int i = blockIdx.x * 256 + threadIdx.x;
    if (i < BHc * Mc * DHc) ctx[i] = 0.0f;
    if (i < BHc * Mc) ksum[i] = 0.0f;
}

// --------------------------------- k_sum -----------------------------------
// grid (BHc, 8), 256 threads (one per m); coalesced row reads
__global__ __launch_bounds__(256)
void ksum_kernel(const float* __restrict__ kp, float* __restrict__ ksum) {
    int bh = blockIdx.x;
    int n0 = blockIdx.y * (Nc / 8);
    int t = threadIdx.x;
    float s = 0.0f;
    const float* base = kp + ((size_t)bh * Nc + n0) * Mc + t;
    for (int n = 0; n < Nc / 8; n++) s += base[(size_t)n * Mc];
    atomicAdd(&ksum[bh * Mc + t], s);
}

// ------------------------------- ctx = kp^T v ------------------------------
// grid (BHc, 16 splits), 256 threads; thread -> 4 m x 16 d
__global__ __launch_bounds__(256)
void ctx_kernel(const float* __restrict__ kp, const float* __restrict__ qkv,
                float* __restrict__ ctx) {
    int bh = blockIdx.x;
    int split = blockIdx.y;
    int b = bh >> 3, h = bh & 7;
    const int NS = Nc / 16;               // 256 rows per split
    int n0 = split * NS;
    int t = threadIdx.x;
    int tx = t & 63;                      // m-group
    int ty = t >> 6;                      // d-group 0..3

    __shared__ float kps[32][256];
    __shared__ float vs[32][64];

    float acc[4][16];
#pragma unroll
    for (int i = 0; i < 4; i++)
#pragma unroll
        for (int j = 0; j < 16; j++) acc[i][j] = 0.0f;

    for (int nc = 0; nc < NS; nc += 32) {
#pragma unroll
        for (int i = 0; i < 8; i++) {
            int li = t + i * 256;         // float4 index 0..2047
            int r = li >> 6;
            int c = (li & 63) * 4;
            *(float4*)&kps[r][c] =
                *(const float4*)&kp[((size_t)bh * Nc + n0 + nc + r) * Mc + c];
        }
#pragma unroll
        for (int i = 0; i < 2; i++) {
            int li = t + i * 256;         // float4 index 0..511
            int r = li >> 4;
            int c = (li & 15) * 4;
            *(float4*)&vs[r][c] =
                *(const float4*)&qkv[((size_t)(b * Nc + n0 + nc + r)) * QKVW +
                                     2 * Dc + h * DHc + c];
        }
        __syncthreads();

#pragma unroll 4
        for (int nn = 0; nn < 32; nn++) {
            float kv[4];
#pragma unroll
            for (int mm = 0; mm < 4; mm++) kv[mm] = kps[nn][tx + mm * 64];
            float vv[16];
            *(float4*)&vv[0]  = *(float4*)&vs[nn][ty * 16];
            *(float4*)&vv[4]  = *(float4*)&vs[nn][ty * 16 + 4];
            *(float4*)&vv[8]  = *(float4*)&vs[nn][ty * 16 + 8];
            *(float4*)&vv[12] = *(float4*)&vs[nn][ty * 16 + 12];
#pragma unroll
            for (int mm = 0; mm < 4; mm++)
#pragma unroll
                for (int dd = 0; dd < 16; dd++)
                    acc[mm][dd] = fmaf(kv[mm], vv[dd], acc[mm][dd]);
        }
        __syncthreads();
    }

#pragma unroll
    for (int mm = 0; mm < 4; mm++)
#pragma unroll
        for (int dd = 0; dd < 16; dd++)
            atomicAdd(&ctx[((size_t)bh * Mc + tx + mm * 64) * DHc + ty * 16 + dd],
                      acc[mm][dd]);
}

// ------------------------------- d_inv -------------------------------------
// one warp per (bh, n) row
__global__ __launch_bounds__(256)
void dinv_kernel(const float* __restrict__ qp, const float* __restrict__ ksum,
                 float* __restrict__ dinv) {
    int w = threadIdx.x >> 5, lane = threadIdx.x & 31;
    int rr = blockIdx.x * 8 + w;          // 0..65535
    int bh = rr >> 12;
    float s = 0.0f;
#pragma unroll
    for (int j = 0; j < 8; j++) {
        int m = lane + j * 32;
        s += qp[(size_t)rr * Mc + m] * ksum[bh * Mc + m];
    }
#pragma unroll
    for (int o = 16; o > 0; o >>= 1) s += __shfl_down_sync(0xffffffffu, s, o);
    if (lane == 0) dinv[rr] = 1.0f / s;
}

// ---------------------- out = dinv * (qp @ ctx), merge heads ---------------
// grid (Nc/64 n-tiles, BHc), 256 threads; 64x64 tile, 4x4 per thread
__global__ __launch_bounds__(256)
void attnout_kernel(const float* __restrict__ qp, const float* __restrict__ ctx,
                    const float* __restrict__ dinv, float* __restrict__ out) {
    int bh = blockIdx.y;
    int n0 = blockIdx.x * 64;
    int b = bh >> 3, h = bh & 7;
    int t = threadIdx.x;
    int tx = t & 15, ty = t >> 4;

    __shared__ float qs[64][36];
    __shared__ float cs[32][64];

    float acc[4][4];
#pragma unroll
    for (int i = 0; i < 4; i++)
#pragma unroll
        for (int j = 0; j < 4; j++) acc[i][j] = 0.0f;

    for (int k0 = 0; k0 < Mc; k0 += 32) {
#pragma unroll
        for (int i = 0; i < 2; i++) {
            int l = t + i * 256;          // float4 index 0..511
            int r = l >> 3;               // 8 float4 per 32-wide row
            int c = (l & 7) * 4;
            *(float4*)&qs[r][c] =
                *(const float4*)&qp[((size_t)bh * Nc + n0 + r) * Mc + k0 + c];
        }
#pragma unroll
        for (int i = 0; i < 2; i++) {
            int l = t + i * 256;
            int r = l >> 4;               // 16 float4 per 64-wide row
            int c = (l & 15) * 4;
            *(float4*)&cs[r][c] =
                *(const float4*)&ctx[((size_t)bh * Mc + k0 + r) * DHc + c];
        }
        __syncthreads();

#pragma unroll
        for (int k = 0; k < 32; k++) {
            float a[4];
#pragma unroll
            for (int i = 0; i < 4; i++) a[i] = qs[ty * 4 + i][k];
            float bb[4];
            *(float4*)bb = *(float4*)&cs[k][tx * 4];
#pragma unroll
            for (int i = 0; i < 4; i++)
#pragma unroll
                for (int j = 0; j < 4; j++)
                    acc[i][j] = fmaf(a[i], bb[j], acc[i][j]);
        }
        __syncthreads();
    }

#pragma unroll
    for (int i = 0; i < 4; i++) {
        int n = n0 + ty * 4 + i;
        float di = dinv[(size_t)bh * Nc + n];
#pragma unroll
        for (int j = 0; j < 4; j++)
            out[((size_t)(b * Nc + n)) * Dc + h * DHc + tx * 4 + j] = acc[i][j] * di;
    }
}

// ------------------------------- launch ------------------------------------
extern "C" void kernel_launch(void* const* d_in, const int* in_sizes, int n_in,
                              void* d_out, int out_size) {
    (void)in_sizes; (void)n_in; (void)out_size;
    const float* x    = (const float*)d_in[0];
    const float* proj = (const float*)d_in[1];
    const float* ln1g = (const float*)d_in[2];
    const float* ln1b = (const float*)d_in[3];
    const float* Wqkv = (const float*)d_in[4];
    const float* bqkv = (const float*)d_in[5];
    const float* Wo   = (const float*)d_in[6];
    const float* bo   = (const float*)d_in[7];
    const float* ln2g = (const float*)d_in[8];
    const float* ln2b = (const float*)d_in[9];
    const float* Wff1 = (const float*)d_in[10];
    const float* bff1 = (const float*)d_in[11];
    const float* Wff2 = (const float*)d_in[12];
    const float* bff2 = (const float*)d_in[13];
    float* h = (float*)d_out;

    static float *p_ln = 0, *p_qkv = 0, *p_qp = 0, *p_kp = 0, *p_ff = 0,
                 *p_ctx = 0, *p_ksum = 0, *p_kdiag = 0, *p_bmax = 0,
                 *p_hmax = 0, *p_dinv = 0;
    if (!p_ln) {
        cudaGetSymbolAddress((void**)&p_ln, g_ln);
        cudaGetSymbolAddress((void**)&p_qkv, g_qkv);
        cudaGetSymbolAddress((void**)&p_qp, g_qp);
        cudaGetSymbolAddress((void**)&p_kp, g_kp);
        cudaGetSymbolAddress((void**)&p_ff, g_ff);
        cudaGetSymbolAddress((void**)&p_ctx, g_ctx);
        cudaGetSymbolAddress((void**)&p_ksum, g_ksum);
        cudaGetSymbolAddress((void**)&p_kdiag, g_kdiag);
        cudaGetSymbolAddress((void**)&p_bmax, g_bmax);
        cudaGetSymbolAddress((void**)&p_hmax, g_hmax);
        cudaGetSymbolAddress((void**)&p_dinv, g_dinv);
    }

    copy_kernel<<<(ROWSc * Dc) / 256, 256>>>(x, h);

    for (int l = 0; l < DEPTHc; l++) {
        const float* pj = proj + (size_t)l * Mc * DHc;

        ln_kernel<<<ROWSc, 256>>>(h, ln1g + l * Dc, ln1b + l * Dc, p_ln);

        sgemm<EPI_NONE><<<dim3(QKVW / 128, ROWSc / 128), 256>>>(
            p_ln, Wqkv + (size_t)l * Dc * QKVW, bqkv + l * QKVW,
            (const float*)0, p_qkv, ROWSc, QKVW, Dc);

        zero_kernel<<<(BHc * Mc * DHc + 255) / 256, 256>>>(p_ctx, p_ksum);

        featq_kernel<<<dim3(ROWSc, Hc), 256>>>(p_qkv, pj, p_qp);
        featk1_kernel<<<dim3(ROWSc, Hc), 256>>>(p_qkv, pj, p_kp, p_kdiag, p_bmax);
        hmax_kernel<<<BHc, 256>>>(p_bmax, p_hmax);
        featk2_kernel<<<(BHc * Nc * Mc / 4) / 256, 256>>>(p_kp, p_kdiag, p_hmax);

        ksum_kernel<<<dim3(BHc, 8), 256>>>(p_kp, p_ksum);
        ctx_kernel<<<dim3(BHc, 16), 256>>>(p_kp, p_qkv, p_ctx);
        dinv_kernel<<<(BHc * Nc) / 8, 256>>>(p_qp, p_ksum, p_dinv);
        attnout_kernel<<<dim3(Nc / 64, BHc), 256>>>(p_qp, p_ctx, p_dinv, p_ln);

        sgemm<EPI_ADD><<<dim3(Dc / 128, ROWSc / 128), 256>>>(
            p_ln, Wo + (size_t)l * Dc * Dc, bo + l * Dc, h, h, ROWSc, Dc, Dc);

        ln_kernel<<<ROWSc, 256>>>(h, ln2g + l * Dc, ln2b + l * Dc, p_ln);

        sgemm<EPI_GELU><<<dim3(FFc / 128, ROWSc / 128), 256>>>(
            p_ln, Wff1 + (size_t)l * Dc * FFc, bff1 + l * FFc,
            (const float*)0, p_ff, ROWSc, FFc, Dc);

        sgemm<EPI_ADD><<<dim3(Dc / 128, ROWSc / 128), 256>>>(
            p_ff, Wff2 + (size_t)l * FFc * Dc, bff2 + l * Dc, h, h,
            ROWSc, Dc, FFc);
    }
}

// round 2
// speedup vs baseline: 4.0071x; 4.0071x over previous
#include <cuda_runtime.h>
#include <math.h>
#include <stdint.h>

// ---------------------------------------------------------------------------
// SpatioTemporalPerformerEncoder — R2: tf32 mma.sync GEMMs + GEMM-ified FAVOR+
// B=2, T=8, L=512 -> 8192 rows, D=512, H=8, dh=64, m=256, FF=2048, depth=4
// ---------------------------------------------------------------------------

#define Bc     2
#define Hc     8
#define Nc     4096
#define Dc     512
#define DHc    64
#define Mc     256
#define FFc    2048
#define DEPTHc 4
#define ROWSc  8192
#define BHc    16
#define QKVW   1536

#define DN_CONST    0.35355339059327373f   // 64^-0.25
#define DIAG_SCALE  0.0625f                // 0.5*dn*dn
#define RATIO_CONST 0.0625f                // 256^-0.5
#define EPSK        1e-4f
#define LNEPS       1e-5f

// ------------------------- scratch (device globals) ------------------------
__device__ float g_ln   [(size_t)ROWSc * Dc];
__device__ float g_qkv  [(size_t)ROWSc * QKVW];
__device__ float g_qp   [(size_t)BHc * Nc * Mc];
__device__ float g_kp   [(size_t)BHc * Nc * Mc];
__device__ float g_ff   [(size_t)ROWSc * FFc];
__device__ float g_ctx  [BHc * Mc * DHc];
__device__ float g_ksum [BHc * Mc];
__device__ float g_qdiag[BHc * Nc];
__device__ float g_kdiag[BHc * Nc];
__device__ float g_bmax [BHc * Nc];
__device__ float g_hmax [BHc];
__device__ float g_dinv [BHc * Nc];

// ------------------------------ helpers ------------------------------------
__device__ __forceinline__ uint32_t f2tf(float f) {
    uint32_t u;
    asm("cvt.rna.tf32.f32 %0, %1;" : "=r"(u) : "f"(f));
    return u;
}

__device__ __forceinline__ void mma_tf32(float c[4], const uint32_t a[4],
                                         const uint32_t b[2]) {
    asm volatile(
        "mma.sync.aligned.m16n8k8.row.col.f32.tf32.tf32.f32 "
        "{%0,%1,%2,%3}, {%4,%5,%6,%7}, {%8,%9}, {%0,%1,%2,%3};\n"
        : "+f"(c[0]), "+f"(c[1]), "+f"(c[2]), "+f"(c[3])
        : "r"(a[0]), "r"(a[1]), "r"(a[2]), "r"(a[3]), "r"(b[0]), "r"(b[1]));
}

// ------------------------------ copy x -> h --------------------------------
__global__ void copy_kernel(const float* __restrict__ x, float* __restrict__ h) {
    size_t i = (size_t)blockIdx.x * 256 + threadIdx.x;
    h[i] = x[i];
}

// ------------------------------- layernorm ---------------------------------
__global__ __launch_bounds__(256)
void ln_kernel(const float* __restrict__ x, const float* __restrict__ g,
               const float* __restrict__ b, float* __restrict__ out) {
    int row = blockIdx.x;
    int t = threadIdx.x;
    const float* xr = x + (size_t)row * Dc;
    float v0 = xr[t], v1 = xr[t + 256];

    __shared__ float red[256];
    red[t] = v0 + v1;
    __syncthreads();
#pragma unroll
    for (int o = 128; o > 0; o >>= 1) {
        if (t < o) red[t] += red[t + o];
        __syncthreads();
    }
    float mu = red[0] * (1.0f / Dc);
    __syncthreads();

    float d0 = v0 - mu, d1 = v1 - mu;
    red[t] = d0 * d0 + d1 * d1;
    __syncthreads();
#pragma unroll
    for (int o = 128; o > 0; o >>= 1) {
        if (t < o) red[t] += red[t + o];
        __syncthreads();
    }
    float rs = rsqrtf(red[0] * (1.0f / Dc) + LNEPS);

    float* orow = out + (size_t)row * Dc;
    orow[t]       = d0 * rs * g[t]       + b[t];
    orow[t + 256] = d1 * rs * g[t + 256] + b[t + 256];
}

// ------------------------- tf32 tensor-core GEMM ---------------------------
// C = scale * (A[M,K] @ op(B)) (+bias) (+gelu | +residual)
// BM=128, BN=128, BK=16, 256 threads (8 warps as 2x4), warp tile 64x32.
// TRB: B given as [N,K] row-major (we need B^T). BH: batched over b*H heads
// reading A slices out of the packed qkv buffer.
#define EPI_NONE 0
#define EPI_GELU 1
#define EPI_ADD  2

template <int EPI, bool TRB, bool BH>
__global__ __launch_bounds__(256)
void mgemm(const float* __restrict__ A, int lda,
           const float* __restrict__ Bm, int ldb,
           const float* __restrict__ bias, const float* __restrict__ R,
           float* __restrict__ C, int ldc,
           int M, int N, int K, float scale) {
    __shared__ uint32_t As[2][128][20];   // [m][k], stride 20 words
    __shared__ uint32_t Bs[2][16][136];   // [k][n], stride 136 words

    if (BH) {
        int z = blockIdx.z;                 // bh
        int b = z >> 3, h = z & 7;
        A += (size_t)b * Nc * lda + (size_t)h * DHc;
        C += (size_t)z * Nc * ldc;
    }

    int m0 = blockIdx.y * 128, n0 = blockIdx.x * 128;
    int tid = threadIdx.x;
    int lane = tid & 31, warp = tid >> 5;
    int g = lane >> 2, tig = lane & 3;
    int wm = warp >> 2, wn = warp & 3;

    // copy-in indexing
    int ra = tid >> 2;            // 0..63   (A row; also TRB B row)
    int ca = (tid & 3) * 4;       // 0,4,8,12 (k offset)
    int rb = tid >> 5;            // 0..7    (B k-row, !TRB)
    int cb = (tid & 31) * 4;      // 0..124  (B n-col, !TRB)

    float c[4][4][4];
#pragma unroll
    for (int i = 0; i < 4; i++)
#pragma unroll
        for (int j = 0; j < 4; j++)
#pragma unroll
            for (int l = 0; l < 4; l++) c[i][j][l] = 0.0f;

    float4 pa0, pa1, pb0, pb1;

#define LOAD_TILE(t)                                                          \
    {                                                                         \
        int k0 = (t) * 16;                                                    \
        pa0 = *(const float4*)&A[(size_t)(m0 + ra) * lda + k0 + ca];          \
        pa1 = *(const float4*)&A[(size_t)(m0 + ra + 64) * lda + k0 + ca];     \
        if (TRB) {                                                            \
            pb0 = *(const float4*)&Bm[(size_t)(n0 + ra) * ldb + k0 + ca];     \
            pb1 = *(const float4*)&Bm[(size_t)(n0 + ra + 64) * ldb + k0 + ca];\
        } else {                                                              \
            pb0 = *(const float4*)&Bm[(size_t)(k0 + rb) * ldb + n0 + cb];     \
            pb1 = *(const float4*)&Bm[(size_t)(k0 + rb + 8) * ldb + n0 + cb]; \
        }                                                                     \
    }

#define STORE_TILE(buf)                                                       \
    {                                                                         \
        uint4 ua0 = {f2tf(pa0.x), f2tf(pa0.y), f2tf(pa0.z), f2tf(pa0.w)};     \
        uint4 ua1 = {f2tf(pa1.x), f2tf(pa1.y), f2tf(pa1.z), f2tf(pa1.w)};     \
        *(uint4*)&As[buf][ra][ca]      = ua0;                                 \
        *(uint4*)&As[buf][ra + 64][ca] = ua1;                                 \
        if (TRB) {                                                            \
            Bs[buf][ca + 0][ra] = f2tf(pb0.x);                                \
            Bs[buf][ca + 1][ra] = f2tf(pb0.y);                                \
            Bs[buf][ca + 2][ra] = f2tf(pb0.z);                                \
            Bs[buf][ca + 3][ra] = f2tf(pb0.w);                                \
            Bs[buf][ca + 0][ra + 64] = f2tf(pb1.x);                           \
            Bs[buf][ca + 1][ra + 64] = f2tf(pb1.y);                           \
            Bs[buf][ca + 2][ra + 64] = f2tf(pb1.z);                           \
            Bs[buf][ca + 3][ra + 64] = f2tf(pb1.w);                           \
        } else {                                                              \
            uint4 ub0 = {f2tf(pb0.x), f2tf(pb0.y), f2tf(pb0.z), f2tf(pb0.w)}; \
            uint4 ub1 = {f2tf(pb1.x), f2tf(pb1.y), f2tf(pb1.z), f2tf(pb1.w)}; \
            *(uint4*)&Bs[buf][rb][cb]     = ub0;                              \
            *(uint4*)&Bs[buf][rb + 8][cb] = ub1;                              \
        }                                                                     \
    }

    int T = K / 16;
    LOAD_TILE(0)
    STORE_TILE(0)
    __syncthreads();

    for (int t = 0; t < T; t++) {
        if (t + 1 < T) LOAD_TILE(t + 1)

        int buf = t & 1;
#pragma unroll
        for (int kk = 0; kk < 2; kk++) {
            int k = kk * 8;
            uint32_t a[4][4], b[4][2];
#pragma unroll
            for (int mi = 0; mi < 4; mi++) {
                int m = wm * 64 + mi * 16;
                a[mi][0] = As[buf][m + g][k + tig];
                a[mi][1] = As[buf][m + g + 8][k + tig];
                a[mi][2] = As[buf][m + g][k + tig + 4];
                a[mi][3] = As[buf][m + g + 8][k + tig + 4];
            }
#pragma unroll
            for (int ni = 0; ni < 4; ni++) {
                int n = wn * 32 + ni * 8;
                b[ni][0] = Bs[buf][k + tig][n + g];
                b[ni][1] = Bs[buf][k + tig + 4][n + g];
            }
#pragma unroll
            for (int mi = 0; mi < 4; mi++)
#pragma unroll
                for (int ni = 0; ni < 4; ni++)
                    mma_tf32(c[mi][ni], a[mi], b[ni]);
        }

        if (t + 1 < T) STORE_TILE((t + 1) & 1)
        __syncthreads();
    }

#undef LOAD_TILE
#undef STORE_TILE

    // epilogue
#pragma unroll
    for (int mi = 0; mi < 4; mi++) {
#pragma unroll
        for (int ni = 0; ni < 4; ni++) {
            int row = m0 + wm * 64 + mi * 16 + g;
            int col = n0 + wn * 32 + ni * 8 + 2 * tig;
#pragma unroll
            for (int half = 0; half < 2; half++) {
                int r = row + half * 8;
                float v0 = c[mi][ni][half * 2 + 0] * scale;
                float v1 = c[mi][ni][half * 2 + 1] * scale;
                if (bias) { v0 += bias[col]; v1 += bias[col + 1]; }
                if (EPI == EPI_GELU) {
                    v0 = 0.5f * v0 * (1.0f + erff(v0 * 0.70710678118654752f));
                    v1 = 0.5f * v1 * (1.0f + erff(v1 * 0.70710678118654752f));
                }
                if (EPI == EPI_ADD) {
                    v0 += R[(size_t)r * ldc + col];
                    v1 += R[(size_t)r * ldc + col + 1];
                }
                float2 o = {v0, v1};
                *(float2*)&C[(size_t)r * ldc + col] = o;
            }
        }
    }
}

// ------------------- diag: per-(bh,row) 0.5*dn^2*|q|^2, |k|^2 --------------
__global__ __launch_bounds__(256)
void diag_kernel(const float* __restrict__ qkv, float* __restrict__ qdiag,
                 float* __restrict__ kdiag) {
    int row = blockIdx.x;
    int w = threadIdx.x >> 5, lane = threadIdx.x & 31;
    const float* base = qkv + (size_t)row * QKVW + w * DHc;
    float q0 = base[lane], q1 = base[lane + 32];
    float k0 = base[Dc + lane], k1 = base[Dc + lane + 32];
    float sq = q0 * q0 + q1 * q1;
    float sk = k0 * k0 + k1 * k1;
#pragma unroll
    for (int o = 16; o > 0; o >>= 1) {
        sq += __shfl_down_sync(0xffffffffu, sq, o);
        sk += __shfl_down_sync(0xffffffffu, sk, o);
    }
    if (lane == 0) {
        int bh = (row >> 12) * Hc + w;
        int n = row & (Nc - 1);
        qdiag[(size_t)bh * Nc + n] = sq * DIAG_SCALE;
        kdiag[(size_t)bh * Nc + n] = sk * DIAG_SCALE;
    }
}

// ---------------- q features: per-row max + exp (in place) -----------------
__global__ __launch_bounds__(256)
void featq_finish(float* __restrict__ qp, const float* __restrict__ qdiag) {
    int w = threadIdx.x >> 5, lane = threadIdx.x & 31;
    int rr = blockIdx.x * 8 + w;
    float* p = qp + (size_t)rr * Mc + lane * 8;
    float4 v0 = *(float4*)p;
    float4 v1 = *(float4*)(p + 4);
    float mx = fmaxf(fmaxf(fmaxf(v0.x, v0.y), fmaxf(v0.z, v0.w)),
                     fmaxf(fmaxf(v1.x, v1.y), fmaxf(v1.z, v1.w)));
#pragma unroll
    for (int o = 16; o > 0; o >>= 1)
        mx = fmaxf(mx, __shfl_xor_sync(0xffffffffu, mx, o));
    float sub = qdiag[rr] + mx;
    v0.x = RATIO_CONST * (expf(v0.x - sub) + EPSK);
    v0.y = RATIO_CONST * (expf(v0.y - sub) + EPSK);
    v0.z = RATIO_CONST * (expf(v0.z - sub) + EPSK);
    v0.w = RATIO_CONST * (expf(v0.w - sub) + EPSK);
    v1.x = RATIO_CONST * (expf(v1.x - sub) + EPSK);
    v1.y = RATIO_CONST * (expf(v1.y - sub) + EPSK);
    v1.z = RATIO_CONST * (expf(v1.z - sub) + EPSK);
    v1.w = RATIO_CONST * (expf(v1.w - sub) + EPSK);
    *(float4*)p = v0;
    *(float4*)(p + 4) = v1;
}

// ---------------- k features pass A: per-row max ---------------------------
__global__ __launch_bounds__(256)
void featk_rowmax(const float* __restrict__ kp, float* __restrict__ bmax) {
    int w = threadIdx.x >> 5, lane = threadIdx.x & 31;
    int rr = blockIdx.x * 8 + w;
    const float* p = kp + (size_t)rr * Mc + lane * 8;
    float4 v0 = *(const float4*)p;
    float4 v1 = *(const float4*)(p + 4);
    float mx = fmaxf(fmaxf(fmaxf(v0.x, v0.y), fmaxf(v0.z, v0.w)),
                     fmaxf(fmaxf(v1.x, v1.y), fmaxf(v1.z, v1.w)));
#pragma unroll
    for (int o = 16; o > 0; o >>= 1)
        mx = fmaxf(mx, __shfl_xor_sync(0xffffffffu, mx, o));
    if (lane == 0) bmax[rr] = mx;
}

// ------------------------- per-head global max -----------------------------
__global__ __launch_bounds__(256)
void hmax_kernel(const float* __restrict__ bmax, float* __restrict__ hmax) {
    int bh = blockIdx.x;
    int t = threadIdx.x;
    float m = -1e30f;
    for (int i = t; i < Nc; i += 256) m = fmaxf(m, bmax[(size_t)bh * Nc + i]);
#pragma unroll
    for (int o = 16; o > 0; o >>= 1) m = fmaxf(m, __shfl_xor_sync(0xffffffffu, m, o));
    __shared__ float w[8];
    if ((t & 31) == 0) w[t >> 5] = m;
    __syncthreads();
    if (t == 0) {
        float mm = w[0];
#pragma unroll
        for (int i = 1; i < 8; i++) mm = fmaxf(mm, w[i]);
        hmax[bh] = mm;
    }
}

// ---------------- k features pass B: exp (in place) ------------------------
__global__ __launch_bounds__(256)
void featk2_kernel(float* __restrict__ kp, const float* __restrict__ kdiag,
                   const float* __restrict__ hmax) {
    size_t i4 = (size_t)blockIdx.x * 256 + threadIdx.x;
    size_t idx = i4 * 4;
    int bh = (int)(idx >> 20);
    int n  = (int)((idx >> 8) & (Nc - 1));
    float sub = kdiag[(size_t)bh * Nc + n] + hmax[bh];
    float4 v = *(float4*)&kp[idx];
    v.x = RATIO_CONST * (expf(v.x - sub) + EPSK);
    v.y = RATIO_CONST * (expf(v.y - sub) + EPSK);
    v.z = RATIO_CONST * (expf(v.z - sub) + EPSK);
    v.w = RATIO_CONST * (expf(v.w - sub) + EPSK);
    *(float4*)&kp[idx] = v;
}

// ---------------------------- zero ctx / ksum ------------------------------
__global__ void zero_kernel(float* __restrict__ ctx, float* __restrict__ ksum) {
    int i = blockIdx.x * 256 + threadIdx.x;
    if (i < BHc * Mc * DHc) ctx[i] = 0.0f;
    if (i < BHc * Mc) ksum[i] = 0.0f;
}

// --------------------------------- k_sum -----------------------------------
__global__ __launch_bounds__(256)
void ksum_kernel(const float* __restrict__ kp, float* __restrict__ ksum) {
    int bh = blockIdx.x;
    int n0 = blockIdx.y * (Nc / 8);
    int t = threadIdx.x;
    float s = 0.0f;
    const float* base = kp + ((size_t)bh * Nc + n0) * Mc + t;
    for (int n = 0; n < Nc / 8; n++) s += base[(size_t)n * Mc];
    atomicAdd(&ksum[bh * Mc + t], s);
}

// ------------------------------- ctx = kp^T v ------------------------------
__global__ __launch_bounds__(256)
void ctx_kernel(const float* __restrict__ kp, const float* __restrict__ qkv,
                float* __restrict__ ctx) {
    int bh = blockIdx.x;
    int split = blockIdx.y;
    int b = bh >> 3, h = bh & 7;
    const int NS = Nc / 16;
    int n0 = split * NS;
    int t = threadIdx.x;
    int tx = t & 63;
    int ty = t >> 6;

    __shared__ float kps[32][256];
    __shared__ float vs[32][64];

    float acc[4][16];
#pragma unroll
    for (int i = 0; i < 4; i++)
#pragma unroll
        for (int j = 0; j < 16; j++) acc[i][j] = 0.0f;

    for (int nc = 0; nc < NS; nc += 32) {
#pragma unroll
        for (int i = 0; i < 8; i++) {
            int li = t + i * 256;
            int r = li >> 6;
            int cc = (li & 63) * 4;
            *(float4*)&kps[r][cc] =
                *(const float4*)&kp[((size_t)bh * Nc + n0 + nc + r) * Mc + cc];
        }
#pragma unroll
        for (int i = 0; i < 2; i++) {
            int li = t + i * 256;
            int r = li >> 4;
            int cc = (li & 15) * 4;
            *(float4*)&vs[r][cc] =
                *(const float4*)&qkv[((size_t)(b * Nc + n0 + nc + r)) * QKVW +
                                     2 * Dc + h * DHc + cc];
        }
        __syncthreads();

#pragma unroll 4
        for (int nn = 0; nn < 32; nn++) {
            float kv[4];
#pragma unroll
            for (int mm = 0; mm < 4; mm++) kv[mm] = kps[nn][tx + mm * 64];
            float vv[16];
            *(float4*)&vv[0]  = *(float4*)&vs[nn][ty * 16];
            *(float4*)&vv[4]  = *(float4*)&vs[nn][ty * 16 + 4];
            *(float4*)&vv[8]  = *(float4*)&vs[nn][ty * 16 + 8];
            *(float4*)&vv[12] = *(float4*)&vs[nn][ty * 16 + 12];
#pragma unroll
            for (int mm = 0; mm < 4; mm++)
#pragma unroll
                for (int dd = 0; dd < 16; dd++)
                    acc[mm][dd] = fmaf(kv[mm], vv[dd], acc[mm][dd]);
        }
        __syncthreads();
    }

#pragma unroll
    for (int mm = 0; mm < 4; mm++)
#pragma unroll
        for (int dd = 0; dd < 16; dd++)
            atomicAdd(&ctx[((size_t)bh * Mc + tx + mm * 64) * DHc + ty * 16 + dd],
                      acc[mm][dd]);
}

// ------------------------------- d_inv -------------------------------------
__global__ __launch_bounds__(256)
void dinv_kernel(const float* __restrict__ qp, const float* __restrict__ ksum,
                 float* __restrict__ dinv) {
    int w = threadIdx.x >> 5, lane = threadIdx.x & 31;
    int rr = blockIdx.x * 8 + w;
    int bh = rr >> 12;
    float s = 0.0f;
#pragma unroll
    for (int j = 0; j < 8; j++) {
        int m = lane + j * 32;
        s += qp[(size_t)rr * Mc + m] * ksum[bh * Mc + m];
    }
#pragma unroll
    for (int o = 16; o > 0; o >>= 1) s += __shfl_down_sync(0xffffffffu, s, o);
    if (lane == 0) dinv[rr] = 1.0f / s;
}

// ---------------------- out = dinv * (qp @ ctx), merge heads ---------------
__global__ __launch_bounds__(256)
void attnout_kernel(const float* __restrict__ qp, const float* __restrict__ ctx,
                    const float* __restrict__ dinv, float* __restrict__ out) {
    int bh = blockIdx.y;
    int n0 = blockIdx.x * 64;
    int b = bh >> 3, h = bh & 7;
    int t = threadIdx.x;
    int tx = t & 15, ty = t >> 4;

    __shared__ float qs[64][36];
    __shared__ float cs[32][64];

    float acc[4][4];
#pragma unroll
    for (int i = 0; i < 4; i++)
#pragma unroll
        for (int j = 0; j < 4; j++) acc[i][j] = 0.0f;

    for (int k0 = 0; k0 < Mc; k0 += 32) {
#pragma unroll
        for (int i = 0; i < 2; i++) {
            int l = t + i * 256;
            int r = l >> 3;
            int cc = (l & 7) * 4;
            *(float4*)&qs[r][cc] =
                *(const float4*)&qp[((size_t)bh * Nc + n0 + r) * Mc + k0 + cc];
        }
#pragma unroll
        for (int i = 0; i < 2; i++) {
            int l = t + i * 256;
            int r = l >> 4;
            int cc = (l & 15) * 4;
            *(float4*)&cs[r][cc] =
                *(const float4*)&ctx[((size_t)bh * Mc + k0 + r) * DHc + cc];
        }
        __syncthreads();

#pragma unroll
        for (int k = 0; k < 32; k++) {
            float a[4];
#pragma unroll
            for (int i = 0; i < 4; i++) a[i] = qs[ty * 4 + i][k];
            float bb[4];
            *(float4*)bb = *(float4*)&cs[k][tx * 4];
#pragma unroll
            for (int i = 0; i < 4; i++)
#pragma unroll
                for (int j = 0; j < 4; j++)
                    acc[i][j] = fmaf(a[i], bb[j], acc[i][j]);
        }
        __syncthreads();
    }

#pragma unroll
    for (int i = 0; i < 4; i++) {
        int n = n0 + ty * 4 + i;
        float di = dinv[(size_t)bh * Nc + n];
#pragma unroll
        for (int j = 0; j < 4; j++)
            out[((size_t)(b * Nc + n)) * Dc + h * DHc + tx * 4 + j] = acc[i][j] * di;
    }
}

// ------------------------------- launch ------------------------------------
extern "C" void kernel_launch(void* const* d_in, const int* in_sizes, int n_in,
                              void* d_out, int out_size) {
    (void)in_sizes; (void)n_in; (void)out_size;
    const float* x    = (const float*)d_in[0];
    const float* proj = (const float*)d_in[1];
    const float* ln1g = (const float*)d_in[2];
    const float* ln1b = (const float*)d_in[3];
    const float* Wqkv = (const float*)d_in[4];
    const float* bqkv = (const float*)d_in[5];
    const float* Wo   = (const float*)d_in[6];
    const float* bo   = (const float*)d_in[7];
    const float* ln2g = (const float*)d_in[8];
    const float* ln2b = (const float*)d_in[9];
    const float* Wff1 = (const float*)d_in[10];
    const float* bff1 = (const float*)d_in[11];
    const float* Wff2 = (const float*)d_in[12];
    const float* bff2 = (const float*)d_in[13];
    float* h = (float*)d_out;

    static float *p_ln = 0, *p_qkv = 0, *p_qp = 0, *p_kp = 0, *p_ff = 0,
                 *p_ctx = 0, *p_ksum = 0, *p_qdiag = 0, *p_kdiag = 0,
                 *p_bmax = 0, *p_hmax = 0, *p_dinv = 0;
    if (!p_ln) {
        cudaGetSymbolAddress((void**)&p_ln, g_ln);
        cudaGetSymbolAddress((void**)&p_qkv, g_qkv);
        cudaGetSymbolAddress((void**)&p_qp, g_qp);
        cudaGetSymbolAddress((void**)&p_kp, g_kp);
        cudaGetSymbolAddress((void**)&p_ff, g_ff);
        cudaGetSymbolAddress((void**)&p_ctx, g_ctx);
        cudaGetSymbolAddress((void**)&p_ksum, g_ksum);
        cudaGetSymbolAddress((void**)&p_qdiag, g_qdiag);
        cudaGetSymbolAddress((void**)&p_kdiag, g_kdiag);
        cudaGetSymbolAddress((void**)&p_bmax, g_bmax);
        cudaGetSymbolAddress((void**)&p_hmax, g_hmax);
        cudaGetSymbolAddress((void**)&p_dinv, g_dinv);
    }

    copy_kernel<<<(ROWSc * Dc) / 256, 256>>>(x, h);

    for (int l = 0; l < DEPTHc; l++) {
        const float* pj = proj + (size_t)l * Mc * DHc;

        ln_kernel<<<ROWSc, 256>>>(h, ln1g + l * Dc, ln1b + l * Dc, p_ln);
        zero_kernel<<<(BHc * Mc * DHc + 255) / 256, 256>>>(p_ctx, p_ksum);

        // QKV projection: [8192x512] @ [512x1536]      (launch index 3 on layer 0)
        mgemm<EPI_NONE, false, false><<<dim3(QKVW / 128, ROWSc / 128, 1), 256>>>(
            p_ln, Dc, Wqkv + (size_t)l * Dc * QKVW, QKVW,
            bqkv + l * QKVW, (const float*)0, p_qkv, QKVW,
            ROWSc, QKVW, Dc, 1.0f);

        // dd_q[bh] = Q_h @ proj^T * dn : batched [4096x64]@[64x256]
        mgemm<EPI_NONE, true, true><<<dim3(Mc / 128, Nc / 128, BHc), 256>>>(
            p_qkv, QKVW, pj, DHc,
            (const float*)0, (const float*)0, p_qp, Mc,
            Nc, Mc, DHc, DN_CONST);

        // dd_k
        mgemm<EPI_NONE, true, true><<<dim3(Mc / 128, Nc / 128, BHc), 256>>>(
            p_qkv + Dc, QKVW, pj, DHc,
            (const float*)0, (const float*)0, p_kp, Mc,
            Nc, Mc, DHc, DN_CONST);

        diag_kernel<<<ROWSc, 256>>>(p_qkv, p_qdiag, p_kdiag);

        featq_finish<<<(BHc * Nc) / 8, 256>>>(p_qp, p_qdiag);
        featk_rowmax<<<(BHc * Nc) / 8, 256>>>(p_kp, p_bmax);
        hmax_kernel<<<BHc, 256>>>(p_bmax, p_hmax);
        featk2_kernel<<<(BHc * Nc * Mc / 4) / 256, 256>>>(p_kp, p_kdiag, p_hmax);

        ksum_kernel<<<dim3(BHc, 8), 256>>>(p_kp, p_ksum);
        ctx_kernel<<<dim3(BHc, 16), 256>>>(p_kp, p_qkv, p_ctx);
        dinv_kernel<<<(BHc * Nc) / 8, 256>>>(p_qp, p_ksum, p_dinv);
        attnout_kernel<<<dim3(Nc / 64, BHc), 256>>>(p_qp, p_ctx, p_dinv, p_ln);

        // Wo + residual
        mgemm<EPI_ADD, false, false><<<dim3(Dc / 128, ROWSc / 128, 1), 256>>>(
            p_ln, Dc, Wo + (size_t)l * Dc * Dc, Dc,
            bo + l * Dc, h, h, Dc, ROWSc, Dc, Dc, 1.0f);

        ln_kernel<<<ROWSc, 256>>>(h, ln2g + l * Dc, ln2b + l * Dc, p_ln);

        // FF1 + gelu
        mgemm<EPI_GELU, false, false><<<dim3(FFc / 128, ROWSc / 128, 1), 256>>>(
            p_ln, Dc, Wff1 + (size_t)l * Dc * FFc, FFc,
            bff1 + l * FFc, (const float*)0, p_ff, FFc,
            ROWSc, FFc, Dc, 1.0f);

        // FF2 + residual
        mgemm<EPI_ADD, false, false><<<dim3(Dc / 128, ROWSc / 128, 1), 256>>>(
            p_ff, FFc, Wff2 + (size_t)l * FFc * Dc, Dc,
            bff2 + l * Dc, h, h, Dc, ROWSc, Dc, FFc, 1.0f);
    }
}